// round 1
// baseline (speedup 1.0000x reference)
#include <cuda_runtime.h>
#include <math.h>
#include <stdint.h>

#define S_LEN   2048
#define HID     2048
#define NH      32
#define NKV     8
#define HD      64
#define KV_W    (NKV*HD)   // 512

// ---------------- scratch (no allocs allowed) ----------------
__device__ float g_q[S_LEN * HID];        // 16 MB
__device__ float g_k[S_LEN * KV_W];       // 4 MB
__device__ float g_v[S_LEN * KV_W];       // 4 MB
__device__ float g_attn[S_LEN * HID];     // 16 MB

// ---------------- SGEMM: C[M,N] = A[M,K] @ B[K,N], row-major ----------------
// BM=128, BN=128, BK=8, TM=TN=8, 256 threads. All dims are exact multiples.
template<int BM, int BN, int BK, int TM, int TN>
__global__ __launch_bounds__(256) void sgemm_k(
    const float* __restrict__ A, const float* __restrict__ B,
    float* __restrict__ C, int M, int N, int K)
{
    __shared__ float As[BK][BM];
    __shared__ float Bs[BK][BN];

    const int t  = threadIdx.x;
    const int bx = blockIdx.x;   // N blocks
    const int by = blockIdx.y;   // M blocks
    const int tx = t % (BN / TN);    // 0..15
    const int ty = t / (BN / TN);    // 0..15

    const float* Ab = A + (size_t)by * BM * K;
    const float* Bb = B + (size_t)bx * BN;

    float acc[TM][TN];
    #pragma unroll
    for (int i = 0; i < TM; i++)
        #pragma unroll
        for (int j = 0; j < TN; j++) acc[i][j] = 0.f;

    const int arow = t >> 1;          // 0..127
    const int acol = (t & 1) * 4;     // 0 or 4
    const int brow = t >> 5;          // 0..7
    const int bcol = (t & 31) * 4;    // 0..124

    for (int k0 = 0; k0 < K; k0 += BK) {
        float4 a4 = *(const float4*)(Ab + (size_t)arow * K + k0 + acol);
        As[acol + 0][arow] = a4.x;
        As[acol + 1][arow] = a4.y;
        As[acol + 2][arow] = a4.z;
        As[acol + 3][arow] = a4.w;
        *(float4*)&Bs[brow][bcol] =
            *(const float4*)(Bb + (size_t)(k0 + brow) * N + bcol);
        __syncthreads();

        #pragma unroll
        for (int k = 0; k < BK; k++) {
            float ra[TM], rb[TN];
            *(float4*)&ra[0] = *(const float4*)&As[k][ty * TM];
            *(float4*)&ra[4] = *(const float4*)&As[k][ty * TM + 4];
            *(float4*)&rb[0] = *(const float4*)&Bs[k][tx * TN];
            *(float4*)&rb[4] = *(const float4*)&Bs[k][tx * TN + 4];
            #pragma unroll
            for (int i = 0; i < TM; i++)
                #pragma unroll
                for (int j = 0; j < TN; j++)
                    acc[i][j] += ra[i] * rb[j];
        }
        __syncthreads();
    }

    float* Cb = C + (size_t)(by * BM + ty * TM) * N + bx * BN + tx * TN;
    #pragma unroll
    for (int i = 0; i < TM; i++) {
        *(float4*)(Cb + (size_t)i * N)     = *(float4*)&acc[i][0];
        *(float4*)(Cb + (size_t)i * N + 4) = *(float4*)&acc[i][4];
    }
}

// ---------------- RoPE (in place on g_q, g_k) + q-scale 1/8 ----------------
// One thread per (s, head, d-pair). Heads 0..NH-1 -> Q, NH..NH+NKV-1 -> K.
__global__ void rope_k(float* __restrict__ q, float* __restrict__ k,
                       const int* __restrict__ pos_ids)
{
    int idx = blockIdx.x * blockDim.x + threadIdx.x;
    const int total = S_LEN * (NH + NKV) * (HD / 2);
    if (idx >= total) return;

    int d    = idx & 31;                 // 0..31 (HD/2)
    int rest = idx >> 5;
    int h    = rest % (NH + NKV);
    int s    = rest / (NH + NKV);

    float pos = (float)pos_ids[s];
    // inv_freq = 10000^{-d/32}
    float inv = __powf(10000.0f, -(float)d * (1.0f / 32.0f));
    float ang = pos * inv;
    float c, sn;
    __sincosf(ang, &sn, &c);

    if (h < NH) {
        float* p = q + (size_t)s * HID + h * HD;
        float x1 = p[d], x2 = p[d + 32];
        p[d]      = (x1 * c - x2 * sn) * 0.125f;   // 1/sqrt(64)
        p[d + 32] = (x2 * c + x1 * sn) * 0.125f;
    } else {
        float* p = k + (size_t)s * KV_W + (h - NH) * HD;
        float x1 = p[d], x2 = p[d + 32];
        p[d]      = x1 * c - x2 * sn;
        p[d + 32] = x2 * c + x1 * sn;
    }
}

// ---------------- Flash attention (causal), fp32 ----------------
// Grid: (S/64, NH). 256 threads = 8 warps; warp w owns q-rows [w*8, w*8+8).
// K-tiles of 32 keys; lane j owns key j of the tile. Online softmax.
#define AQ 64
#define AK 32
#define KPAD 68   // 68*4B = 272B rows: 16B aligned, conflict-free LDS.128

__global__ __launch_bounds__(256, 2) void attn_k(
    const float* __restrict__ Q, const float* __restrict__ K,
    const float* __restrict__ V, float* __restrict__ O)
{
    __shared__ float Qs[AQ][HD];        // 16 KB
    __shared__ float Ks[AK][KPAD];      // 8.5 KB
    __shared__ float Vs[AK][HD];        // 8 KB
    __shared__ float Ps[8][8][AK];      // 8 KB

    const int qt  = blockIdx.x;
    const int h   = blockIdx.y;
    const int kvh = h >> 2;            // repeat_interleave: head h -> kv h/4
    const int t = threadIdx.x, w = t >> 5, lane = t & 31;
    const int q0 = qt * AQ;

    // load Q tile
    for (int i = t; i < AQ * HD / 4; i += 256) {
        int r = i >> 4, c = (i & 15) * 4;
        *(float4*)&Qs[r][c] =
            *(const float4*)(Q + (size_t)(q0 + r) * HID + h * HD + c);
    }

    float m[8], l[8], a0[8], a1[8];
    #pragma unroll
    for (int r = 0; r < 8; r++) { m[r] = -1e30f; l[r] = 0.f; a0[r] = 0.f; a1[r] = 0.f; }

    const int nkt = (qt + 1) * (AQ / AK);   // causal: only tiles with k0 <= q0+63
    for (int kt = 0; kt < nkt; kt++) {
        const int k0 = kt * AK;
        __syncthreads();
        // load K,V tiles (2048 floats each)
        for (int i = t; i < AK * HD / 4; i += 256) {
            int r = i >> 4, c = (i & 15) * 4;
            *(float4*)&Ks[r][c] =
                *(const float4*)(K + (size_t)(k0 + r) * KV_W + kvh * HD + c);
            *(float4*)&Vs[r][c] =
                *(const float4*)(V + (size_t)(k0 + r) * KV_W + kvh * HD + c);
        }
        __syncthreads();

        // scores: lane's key = k0+lane; 8 rows per warp
        float sc[8];
        #pragma unroll
        for (int r = 0; r < 8; r++) sc[r] = 0.f;
        #pragma unroll
        for (int dc = 0; dc < HD; dc += 4) {
            float4 kf = *(const float4*)&Ks[lane][dc];
            #pragma unroll
            for (int r = 0; r < 8; r++) {
                float4 qf = *(const float4*)&Qs[w * 8 + r][dc];
                sc[r] += qf.x * kf.x + qf.y * kf.y + qf.z * kf.z + qf.w * kf.w;
            }
        }

        // online softmax update per row
        #pragma unroll
        for (int r = 0; r < 8; r++) {
            const int qglob = q0 + w * 8 + r;
            float s = (k0 + lane > qglob) ? -1e30f : sc[r];
            float tm = s;
            #pragma unroll
            for (int o = 16; o > 0; o >>= 1)
                tm = fmaxf(tm, __shfl_xor_sync(0xffffffffu, tm, o));
            float nm   = fmaxf(m[r], tm);
            float corr = __expf(m[r] - nm);
            float p    = __expf(s - nm);
            float ts = p;
            #pragma unroll
            for (int o = 16; o > 0; o >>= 1)
                ts += __shfl_xor_sync(0xffffffffu, ts, o);
            l[r] = l[r] * corr + ts;
            m[r] = nm;
            a0[r] *= corr;
            a1[r] *= corr;
            Ps[w][r][lane] = p;
        }
        __syncwarp();

        // accum: lane owns dims (2*lane, 2*lane+1)
        #pragma unroll
        for (int j0 = 0; j0 < AK; j0 += 4) {
            float2 v0 = *(const float2*)&Vs[j0 + 0][2 * lane];
            float2 v1 = *(const float2*)&Vs[j0 + 1][2 * lane];
            float2 v2 = *(const float2*)&Vs[j0 + 2][2 * lane];
            float2 v3 = *(const float2*)&Vs[j0 + 3][2 * lane];
            #pragma unroll
            for (int r = 0; r < 8; r++) {
                float4 pf = *(const float4*)&Ps[w][r][j0];
                a0[r] += pf.x * v0.x + pf.y * v1.x + pf.z * v2.x + pf.w * v3.x;
                a1[r] += pf.x * v0.y + pf.y * v1.y + pf.z * v2.y + pf.w * v3.y;
            }
        }
    }

    // epilogue: O[s, h*64 + d]
    #pragma unroll
    for (int r = 0; r < 8; r++) {
        const int qg = q0 + w * 8 + r;
        float inv = 1.0f / l[r];
        float2 o2 = make_float2(a0[r] * inv, a1[r] * inv);
        *(float2*)(O + (size_t)qg * HID + h * HD + 2 * lane) = o2;
    }
}

// ---------------- launch ----------------
extern "C" void kernel_launch(void* const* d_in, const int* in_sizes, int n_in,
                              void* d_out, int out_size)
{
    const float* X   = (const float*)d_in[0];   // hidden_states [1,2048,2048]
    // d_in[1] = attention_mask (exactly causal -1e9; handled analytically)
    const int*   pid = (const int*)d_in[2];     // position_ids [1,2048]
    const float* Wq  = (const float*)d_in[3];
    const float* Wk  = (const float*)d_in[4];
    const float* Wv  = (const float*)d_in[5];
    const float* Wo  = (const float*)d_in[6];
    float* out = (float*)d_out;

    float *q, *k, *v, *ao;
    cudaGetSymbolAddress((void**)&q,  g_q);
    cudaGetSymbolAddress((void**)&k,  g_k);
    cudaGetSymbolAddress((void**)&v,  g_v);
    cudaGetSymbolAddress((void**)&ao, g_attn);

    // projections
    sgemm_k<128,128,8,8,8><<<dim3(HID / 128, S_LEN / 128), 256>>>(X, Wq, q, S_LEN, HID, HID);
    sgemm_k<128,128,8,8,8><<<dim3(KV_W / 128, S_LEN / 128), 256>>>(X, Wk, k, S_LEN, KV_W, HID);
    sgemm_k<128,128,8,8,8><<<dim3(KV_W / 128, S_LEN / 128), 256>>>(X, Wv, v, S_LEN, KV_W, HID);

    // RoPE on q,k (+ q scale)
    {
        int total = S_LEN * (NH + NKV) * (HD / 2);
        rope_k<<<(total + 255) / 256, 256>>>(q, k, pid);
    }

    // causal flash attention
    attn_k<<<dim3(S_LEN / AQ, NH), 256>>>(q, k, v, ao);

    // output projection
    sgemm_k<128,128,8,8,8><<<dim3(HID / 128, S_LEN / 128), 256>>>(ao, Wo, out, S_LEN, HID, HID);
}

// round 2
// speedup vs baseline: 1.8916x; 1.8916x over previous
#include <cuda_runtime.h>
#include <cuda_bf16.h>
#include <math.h>
#include <stdint.h>

#define S_LEN 2048
#define HID   2048
#define NH    32
#define NKV   8
#define HD    64
#define KVW   1024          // combined [K|V] width (8 kv-heads * 64 * 2)

// ---------------- scratch (no allocs allowed) ----------------
__device__ float g_q   [S_LEN * HID];   // 16 MB
__device__ float g_kv  [S_LEN * KVW];   //  8 MB  (cols 0..511 = K, 512..1023 = V)
__device__ float g_attn[S_LEN * HID];   // 16 MB

// bf16 hi/lo split buffers
__device__ __nv_bfloat16 g_Xhi [S_LEN * HID], g_Xlo [S_LEN * HID];
__device__ __nv_bfloat16 g_Wqhi[HID * HID],   g_Wqlo[HID * HID];
__device__ __nv_bfloat16 g_Wkvhi[HID * KVW],  g_Wkvlo[HID * KVW];
__device__ __nv_bfloat16 g_Wohi[HID * HID],   g_Wolo[HID * HID];
__device__ __nv_bfloat16 g_Ahi [S_LEN * HID], g_Alo [S_LEN * HID];

// ---------------- fp32 -> bf16 hi/lo split ----------------
__global__ void split_k(const float* __restrict__ in,
                        __nv_bfloat16* __restrict__ hi,
                        __nv_bfloat16* __restrict__ lo, int n)
{
    int i = blockIdx.x * 256 + threadIdx.x;
    if (i >= n) return;
    float x = in[i];
    __nv_bfloat16 h = __float2bfloat16(x);
    hi[i] = h;
    lo[i] = __float2bfloat16(x - __bfloat162float(h));
}

// split with packed output (for concatenating Wk|Wv into Wkv)
__global__ void split_pack_k(const float* __restrict__ in,
                             __nv_bfloat16* __restrict__ hi,
                             __nv_bfloat16* __restrict__ lo,
                             int rows, int cols, int ostride, int ooff)
{
    int i = blockIdx.x * 256 + threadIdx.x;
    if (i >= rows * cols) return;
    int r = i / cols, c = i % cols;
    float x = in[i];
    __nv_bfloat16 h = __float2bfloat16(x);
    int o = r * ostride + ooff + c;
    hi[o] = h;
    lo[o] = __float2bfloat16(x - __bfloat162float(h));
}

// ---------------- tensor-core GEMM: C = Ahi@Bhi + Ahi@Blo + Alo@Bhi ----------------
#define BM 128
#define BN 128
#define BK 32
#define ASTRIDE 40     // bf16 elems: 80B rows -> conflict-free ldmatrix
#define BSTRIDE 136    // bf16 elems: 272B rows -> conflict-free ldmatrix.trans
#define A_TILE (BM * ASTRIDE)                 // 5120 elems
#define B_TILE (BK * BSTRIDE)                 // 4352 elems
#define BUF_ELEMS (2 * A_TILE + 2 * B_TILE)   // 18944 elems (hi+lo for A and B)
#define GEMM_SMEM_BYTES (2 * BUF_ELEMS * 2)   // 75776 bytes (double buffered)

__device__ __forceinline__ uint32_t sptr(const void* p) {
    return (uint32_t)__cvta_generic_to_shared(p);
}
__device__ __forceinline__ void cp16(uint32_t dst, const void* src) {
    asm volatile("cp.async.cg.shared.global [%0], [%1], 16;\n" :: "r"(dst), "l"(src));
}
__device__ __forceinline__ void ldsm_x4(uint32_t* r, uint32_t addr) {
    asm volatile("ldmatrix.sync.aligned.m8n8.x4.shared.b16 {%0,%1,%2,%3}, [%4];\n"
        : "=r"(r[0]), "=r"(r[1]), "=r"(r[2]), "=r"(r[3]) : "r"(addr));
}
__device__ __forceinline__ void ldsm_x4_t(uint32_t* r, uint32_t addr) {
    asm volatile("ldmatrix.sync.aligned.m8n8.x4.trans.shared.b16 {%0,%1,%2,%3}, [%4];\n"
        : "=r"(r[0]), "=r"(r[1]), "=r"(r[2]), "=r"(r[3]) : "r"(addr));
}
__device__ __forceinline__ void mma16816(float* c, const uint32_t* a, const uint32_t* b) {
    asm volatile(
        "mma.sync.aligned.m16n8k16.row.col.f32.bf16.bf16.f32 "
        "{%0,%1,%2,%3}, {%4,%5,%6,%7}, {%8,%9}, {%0,%1,%2,%3};\n"
        : "+f"(c[0]), "+f"(c[1]), "+f"(c[2]), "+f"(c[3])
        : "r"(a[0]), "r"(a[1]), "r"(a[2]), "r"(a[3]), "r"(b[0]), "r"(b[1]));
}

__device__ __forceinline__ void load_tile(
    __nv_bfloat16* sm,
    const __nv_bfloat16* __restrict__ Ah, const __nv_bfloat16* __restrict__ Al,
    const __nv_bfloat16* __restrict__ Bh, const __nv_bfloat16* __restrict__ Bl,
    int K, int N, int m0, int n0, int k0, int t)
{
    // A tile: 128 rows x 32 cols = 512 16B chunks (hi and lo)
    #pragma unroll
    for (int c = t; c < 512; c += 256) {
        int row = c >> 2, col = (c & 3) * 8;
        size_t g = (size_t)(m0 + row) * K + k0 + col;
        uint32_t s = (uint32_t)(row * ASTRIDE + col);
        cp16(sptr(sm + s),          Ah + g);
        cp16(sptr(sm + A_TILE + s), Al + g);
    }
    // B tile: 32 rows x 128 cols = 512 16B chunks (hi and lo)
    #pragma unroll
    for (int c = t; c < 512; c += 256) {
        int row = c >> 4, col = (c & 15) * 8;
        size_t g = (size_t)(k0 + row) * N + n0 + col;
        uint32_t s = (uint32_t)(row * BSTRIDE + col);
        cp16(sptr(sm + 2 * A_TILE + s),          Bh + g);
        cp16(sptr(sm + 2 * A_TILE + B_TILE + s), Bl + g);
    }
}

__global__ __launch_bounds__(256) void mma_gemm(
    const __nv_bfloat16* __restrict__ Ah, const __nv_bfloat16* __restrict__ Al,
    const __nv_bfloat16* __restrict__ Bh, const __nv_bfloat16* __restrict__ Bl,
    float* __restrict__ C, int M, int N, int K)
{
    extern __shared__ __nv_bfloat16 sm[];
    const int t = threadIdx.x, lane = t & 31, w = t >> 5;
    const int wm = w >> 2, wn = w & 3;           // warp tile: 64(M) x 32(N)
    const int m0 = blockIdx.y * BM, n0 = blockIdx.x * BN;

    float acc[4][4][4];
    #pragma unroll
    for (int i = 0; i < 4; i++)
        #pragma unroll
        for (int j = 0; j < 4; j++)
            #pragma unroll
            for (int r = 0; r < 4; r++) acc[i][j][r] = 0.f;

    const int g8  = lane >> 3;      // ldmatrix group 0..3
    const int l8  = lane & 7;

    load_tile(sm, Ah, Al, Bh, Bl, K, N, m0, n0, 0, t);
    asm volatile("cp.async.commit_group;\n");

    const int nk = K / BK;
    for (int kt = 0; kt < nk; kt++) {
        __nv_bfloat16* buf = sm + (kt & 1) * BUF_ELEMS;
        if (kt + 1 < nk) {
            load_tile(sm + ((kt + 1) & 1) * BUF_ELEMS, Ah, Al, Bh, Bl,
                      K, N, m0, n0, (kt + 1) * BK, t);
            asm volatile("cp.async.commit_group;\n");
            asm volatile("cp.async.wait_group 1;\n");
        } else {
            asm volatile("cp.async.wait_group 0;\n");
        }
        __syncthreads();

        #pragma unroll
        for (int ks = 0; ks < 2; ks++) {
            uint32_t ah[4][4], al[4][4], bh[4][2], bl[4][2];
            // A fragments: 4 m16 frags, hi + lo
            #pragma unroll
            for (int i = 0; i < 4; i++) {
                int row = wm * 64 + i * 16 + (g8 & 1) * 8 + l8;
                int col = ks * 16 + (g8 >> 1) * 8;
                ldsm_x4(ah[i], sptr(buf + row * ASTRIDE + col));
                ldsm_x4(al[i], sptr(buf + A_TILE + row * ASTRIDE + col));
            }
            // B fragments: 4 n8 frags via two x4.trans, hi + lo
            #pragma unroll
            for (int jj = 0; jj < 2; jj++) {
                int krow = ks * 16 + (g8 & 1) * 8 + l8;
                int ncol = wn * 32 + jj * 16 + (g8 >> 1) * 8;
                uint32_t r4[4];
                ldsm_x4_t(r4, sptr(buf + 2 * A_TILE + krow * BSTRIDE + ncol));
                bh[2 * jj][0] = r4[0]; bh[2 * jj][1] = r4[1];
                bh[2 * jj + 1][0] = r4[2]; bh[2 * jj + 1][1] = r4[3];
                ldsm_x4_t(r4, sptr(buf + 2 * A_TILE + B_TILE + krow * BSTRIDE + ncol));
                bl[2 * jj][0] = r4[0]; bl[2 * jj][1] = r4[1];
                bl[2 * jj + 1][0] = r4[2]; bl[2 * jj + 1][1] = r4[3];
            }
            // 3-pass split mma
            #pragma unroll
            for (int i = 0; i < 4; i++)
                #pragma unroll
                for (int j = 0; j < 4; j++) {
                    mma16816(acc[i][j], ah[i], bh[j]);
                    mma16816(acc[i][j], ah[i], bl[j]);
                    mma16816(acc[i][j], al[i], bh[j]);
                }
        }
        __syncthreads();
    }

    // epilogue
    #pragma unroll
    for (int i = 0; i < 4; i++)
        #pragma unroll
        for (int j = 0; j < 4; j++) {
            int row = m0 + wm * 64 + i * 16 + (lane >> 2);
            int col = n0 + wn * 32 + j * 8 + (lane & 3) * 2;
            *(float2*)&C[(size_t)row * N + col] =
                make_float2(acc[i][j][0], acc[i][j][1]);
            *(float2*)&C[(size_t)(row + 8) * N + col] =
                make_float2(acc[i][j][2], acc[i][j][3]);
        }
}

// ---------------- RoPE (in place) + q-scale 1/8 ----------------
__global__ void rope_k(float* __restrict__ q, float* __restrict__ kv,
                       const int* __restrict__ pos_ids)
{
    int idx = blockIdx.x * blockDim.x + threadIdx.x;
    const int total = S_LEN * (NH + NKV) * (HD / 2);
    if (idx >= total) return;

    int d    = idx & 31;
    int rest = idx >> 5;
    int h    = rest % (NH + NKV);
    int s    = rest / (NH + NKV);

    float pos = (float)pos_ids[s];
    float inv = __powf(10000.0f, -(float)d * (1.0f / 32.0f));
    float ang = pos * inv;
    float c, sn;
    __sincosf(ang, &sn, &c);

    if (h < NH) {
        float* p = q + (size_t)s * HID + h * HD;
        float x1 = p[d], x2 = p[d + 32];
        p[d]      = (x1 * c - x2 * sn) * 0.125f;
        p[d + 32] = (x2 * c + x1 * sn) * 0.125f;
    } else {
        float* p = kv + (size_t)s * KVW + (h - NH) * HD;   // K half of kv
        float x1 = p[d], x2 = p[d + 32];
        p[d]      = x1 * c - x2 * sn;
        p[d + 32] = x2 * c + x1 * sn;
    }
}

// ---------------- Flash attention (causal), fp32 ----------------
#define AQ 64
#define AK 32
#define KPAD 68

__global__ __launch_bounds__(256, 2) void attn_k(
    const float* __restrict__ Q, const float* __restrict__ KV,
    float* __restrict__ O)
{
    __shared__ float Qs[AQ][HD];
    __shared__ float Ks[AK][KPAD];
    __shared__ float Vs[AK][HD];
    __shared__ float Ps[8][8][AK];

    const int qt  = blockIdx.x;
    const int h   = blockIdx.y;
    const int kvh = h >> 2;
    const int t = threadIdx.x, w = t >> 5, lane = t & 31;
    const int q0 = qt * AQ;

    for (int i = t; i < AQ * HD / 4; i += 256) {
        int r = i >> 4, c = (i & 15) * 4;
        *(float4*)&Qs[r][c] =
            *(const float4*)(Q + (size_t)(q0 + r) * HID + h * HD + c);
    }

    float m[8], l[8], a0[8], a1[8];
    #pragma unroll
    for (int r = 0; r < 8; r++) { m[r] = -1e30f; l[r] = 0.f; a0[r] = 0.f; a1[r] = 0.f; }

    const int nkt = (qt + 1) * (AQ / AK);
    for (int kt = 0; kt < nkt; kt++) {
        const int k0 = kt * AK;
        __syncthreads();
        for (int i = t; i < AK * HD / 4; i += 256) {
            int r = i >> 4, c = (i & 15) * 4;
            *(float4*)&Ks[r][c] =
                *(const float4*)(KV + (size_t)(k0 + r) * KVW + kvh * HD + c);
            *(float4*)&Vs[r][c] =
                *(const float4*)(KV + (size_t)(k0 + r) * KVW + 512 + kvh * HD + c);
        }
        __syncthreads();

        float sc[8];
        #pragma unroll
        for (int r = 0; r < 8; r++) sc[r] = 0.f;
        #pragma unroll
        for (int dc = 0; dc < HD; dc += 4) {
            float4 kf = *(const float4*)&Ks[lane][dc];
            #pragma unroll
            for (int r = 0; r < 8; r++) {
                float4 qf = *(const float4*)&Qs[w * 8 + r][dc];
                sc[r] += qf.x * kf.x + qf.y * kf.y + qf.z * kf.z + qf.w * kf.w;
            }
        }

        #pragma unroll
        for (int r = 0; r < 8; r++) {
            const int qglob = q0 + w * 8 + r;
            float s = (k0 + lane > qglob) ? -1e30f : sc[r];
            float tm = s;
            #pragma unroll
            for (int o = 16; o > 0; o >>= 1)
                tm = fmaxf(tm, __shfl_xor_sync(0xffffffffu, tm, o));
            float nm   = fmaxf(m[r], tm);
            float corr = __expf(m[r] - nm);
            float p    = __expf(s - nm);
            float ts = p;
            #pragma unroll
            for (int o = 16; o > 0; o >>= 1)
                ts += __shfl_xor_sync(0xffffffffu, ts, o);
            l[r] = l[r] * corr + ts;
            m[r] = nm;
            a0[r] *= corr;
            a1[r] *= corr;
            Ps[w][r][lane] = p;
        }
        __syncwarp();

        #pragma unroll
        for (int j0 = 0; j0 < AK; j0 += 4) {
            float2 v0 = *(const float2*)&Vs[j0 + 0][2 * lane];
            float2 v1 = *(const float2*)&Vs[j0 + 1][2 * lane];
            float2 v2 = *(const float2*)&Vs[j0 + 2][2 * lane];
            float2 v3 = *(const float2*)&Vs[j0 + 3][2 * lane];
            #pragma unroll
            for (int r = 0; r < 8; r++) {
                float4 pf = *(const float4*)&Ps[w][r][j0];
                a0[r] += pf.x * v0.x + pf.y * v1.x + pf.z * v2.x + pf.w * v3.x;
                a1[r] += pf.x * v0.y + pf.y * v1.y + pf.z * v2.y + pf.w * v3.y;
            }
        }
    }

    #pragma unroll
    for (int r = 0; r < 8; r++) {
        const int qg = q0 + w * 8 + r;
        float inv = 1.0f / l[r];
        *(float2*)(O + (size_t)qg * HID + h * HD + 2 * lane) =
            make_float2(a0[r] * inv, a1[r] * inv);
    }
}

// ---------------- launch ----------------
extern "C" void kernel_launch(void* const* d_in, const int* in_sizes, int n_in,
                              void* d_out, int out_size)
{
    const float* X   = (const float*)d_in[0];
    const int*   pid = (const int*)d_in[2];
    const float* Wq  = (const float*)d_in[3];
    const float* Wk  = (const float*)d_in[4];
    const float* Wv  = (const float*)d_in[5];
    const float* Wo  = (const float*)d_in[6];
    float* out = (float*)d_out;

    float *q, *kv, *ao;
    cudaGetSymbolAddress((void**)&q,  g_q);
    cudaGetSymbolAddress((void**)&kv, g_kv);
    cudaGetSymbolAddress((void**)&ao, g_attn);
    __nv_bfloat16 *Xh, *Xl, *Wqh, *Wql, *Wkvh, *Wkvl, *Woh, *Wol, *Ah, *Al;
    cudaGetSymbolAddress((void**)&Xh,  g_Xhi);  cudaGetSymbolAddress((void**)&Xl,  g_Xlo);
    cudaGetSymbolAddress((void**)&Wqh, g_Wqhi); cudaGetSymbolAddress((void**)&Wql, g_Wqlo);
    cudaGetSymbolAddress((void**)&Wkvh,g_Wkvhi);cudaGetSymbolAddress((void**)&Wkvl,g_Wkvlo);
    cudaGetSymbolAddress((void**)&Woh, g_Wohi); cudaGetSymbolAddress((void**)&Wol, g_Wolo);
    cudaGetSymbolAddress((void**)&Ah,  g_Ahi);  cudaGetSymbolAddress((void**)&Al,  g_Alo);

    cudaFuncSetAttribute(mma_gemm, cudaFuncAttributeMaxDynamicSharedMemorySize,
                         GEMM_SMEM_BYTES);

    // splits
    split_k<<<(S_LEN * HID) / 256, 256>>>(X,  Xh,  Xl,  S_LEN * HID);
    split_k<<<(HID * HID) / 256, 256>>>(Wq, Wqh, Wql, HID * HID);
    split_pack_k<<<(HID * 512) / 256, 256>>>(Wk, Wkvh, Wkvl, HID, 512, KVW, 0);
    split_pack_k<<<(HID * 512) / 256, 256>>>(Wv, Wkvh, Wkvl, HID, 512, KVW, 512);
    split_k<<<(HID * HID) / 256, 256>>>(Wo, Woh, Wol, HID * HID);

    // projections (tensor cores, bf16x3)
    mma_gemm<<<dim3(HID / BN, S_LEN / BM), 256, GEMM_SMEM_BYTES>>>(
        Xh, Xl, Wqh, Wql, q, S_LEN, HID, HID);
    mma_gemm<<<dim3(KVW / BN, S_LEN / BM), 256, GEMM_SMEM_BYTES>>>(
        Xh, Xl, Wkvh, Wkvl, kv, S_LEN, KVW, HID);

    // RoPE
    {
        int total = S_LEN * (NH + NKV) * (HD / 2);
        rope_k<<<(total + 255) / 256, 256>>>(q, kv, pid);
    }

    // causal flash attention
    attn_k<<<dim3(S_LEN / AQ, NH), 256>>>(q, kv, ao);

    // output projection
    split_k<<<(S_LEN * HID) / 256, 256>>>(ao, Ah, Al, S_LEN * HID);
    mma_gemm<<<dim3(HID / BN, S_LEN / BM), 256, GEMM_SMEM_BYTES>>>(
        Ah, Al, Woh, Wol, out, S_LEN, HID, HID);
}

// round 4
// speedup vs baseline: 3.5158x; 1.8587x over previous
#include <cuda_runtime.h>
#include <cuda_bf16.h>
#include <math.h>
#include <stdint.h>

#define S_LEN 2048
#define HID   2048
#define NH    32
#define NKV   8
#define HD    64
#define KVW   1024          // combined [K|V] width

// ---------------- scratch (no allocs allowed) ----------------
__device__ float g_q [S_LEN * HID];
__device__ float g_kv[S_LEN * KVW];   // cols 0..511 = K, 512..1023 = V

__device__ __nv_bfloat16 g_Xhi [S_LEN * HID], g_Xlo [S_LEN * HID];
__device__ __nv_bfloat16 g_Wqhi[HID * HID],   g_Wqlo[HID * HID];
__device__ __nv_bfloat16 g_Wkvhi[HID * KVW],  g_Wkvlo[HID * KVW];
__device__ __nv_bfloat16 g_Wohi[HID * HID],   g_Wolo[HID * HID];
__device__ __nv_bfloat16 g_Ahi [S_LEN * HID], g_Alo [S_LEN * HID];

// attention operands (bf16 hi/lo after RoPE)
__device__ __nv_bfloat16 g_qh[S_LEN * HID], g_ql[S_LEN * HID];
__device__ __nv_bfloat16 g_kh[S_LEN * 512], g_kl[S_LEN * 512];
__device__ __nv_bfloat16 g_vh[S_LEN * 512], g_vl[S_LEN * 512];

// ---------------- helpers ----------------
__device__ __forceinline__ uint32_t sptr(const void* p) {
    return (uint32_t)__cvta_generic_to_shared(p);
}
__device__ __forceinline__ void cp16(uint32_t dst, const void* src) {
    asm volatile("cp.async.cg.shared.global [%0], [%1], 16;\n" :: "r"(dst), "l"(src));
}
__device__ __forceinline__ void ldsm_x4(uint32_t* r, uint32_t addr) {
    asm volatile("ldmatrix.sync.aligned.m8n8.x4.shared.b16 {%0,%1,%2,%3}, [%4];\n"
        : "=r"(r[0]), "=r"(r[1]), "=r"(r[2]), "=r"(r[3]) : "r"(addr));
}
__device__ __forceinline__ void ldsm_x4_t(uint32_t* r, uint32_t addr) {
    asm volatile("ldmatrix.sync.aligned.m8n8.x4.trans.shared.b16 {%0,%1,%2,%3}, [%4];\n"
        : "=r"(r[0]), "=r"(r[1]), "=r"(r[2]), "=r"(r[3]) : "r"(addr));
}
__device__ __forceinline__ void mma16816(float* c, const uint32_t* a, const uint32_t* b) {
    asm volatile(
        "mma.sync.aligned.m16n8k16.row.col.f32.bf16.bf16.f32 "
        "{%0,%1,%2,%3}, {%4,%5,%6,%7}, {%8,%9}, {%0,%1,%2,%3};\n"
        : "+f"(c[0]), "+f"(c[1]), "+f"(c[2]), "+f"(c[3])
        : "r"(a[0]), "r"(a[1]), "r"(a[2]), "r"(a[3]), "r"(b[0]), "r"(b[1]));
}
__device__ __forceinline__ uint32_t packbf2(float x, float y) {
    __nv_bfloat162 h = __floats2bfloat162_rn(x, y);
    return *(uint32_t*)&h;
}

// ---------------- splits ----------------
__global__ void split_k(const float* __restrict__ in,
                        __nv_bfloat16* __restrict__ hi,
                        __nv_bfloat16* __restrict__ lo, int n)
{
    int i = blockIdx.x * 256 + threadIdx.x;
    if (i >= n) return;
    float x = in[i];
    __nv_bfloat16 h = __float2bfloat16(x);
    hi[i] = h;
    lo[i] = __float2bfloat16(x - __bfloat162float(h));
}

__global__ void split_pack_k(const float* __restrict__ in,
                             __nv_bfloat16* __restrict__ hi,
                             __nv_bfloat16* __restrict__ lo,
                             int rows, int cols, int ostride, int ooff)
{
    int i = blockIdx.x * 256 + threadIdx.x;
    if (i >= rows * cols) return;
    int r = i / cols, c = i % cols;
    float x = in[i];
    __nv_bfloat16 h = __float2bfloat16(x);
    int o = r * ostride + ooff + c;
    hi[o] = h;
    lo[o] = __float2bfloat16(x - __bfloat162float(h));
}

// ---------------- tensor-core GEMM (round-2, known good) ----------------
#define BM 128
#define BN 128
#define BK 32
#define ASTRIDE 40
#define BSTRIDE 136
#define A_TILE (BM * ASTRIDE)
#define B_TILE (BK * BSTRIDE)
#define BUF_ELEMS (2 * A_TILE + 2 * B_TILE)
#define GEMM_SMEM_BYTES (2 * BUF_ELEMS * 2)

__device__ __forceinline__ void load_tile(
    __nv_bfloat16* sm,
    const __nv_bfloat16* __restrict__ Ah, const __nv_bfloat16* __restrict__ Al,
    const __nv_bfloat16* __restrict__ Bh, const __nv_bfloat16* __restrict__ Bl,
    int K, int N, int m0, int n0, int k0, int t)
{
    #pragma unroll
    for (int c = t; c < 512; c += 256) {
        int row = c >> 2, col = (c & 3) * 8;
        size_t g = (size_t)(m0 + row) * K + k0 + col;
        uint32_t s = (uint32_t)(row * ASTRIDE + col);
        cp16(sptr(sm + s),          Ah + g);
        cp16(sptr(sm + A_TILE + s), Al + g);
    }
    #pragma unroll
    for (int c = t; c < 512; c += 256) {
        int row = c >> 4, col = (c & 15) * 8;
        size_t g = (size_t)(k0 + row) * N + n0 + col;
        uint32_t s = (uint32_t)(row * BSTRIDE + col);
        cp16(sptr(sm + 2 * A_TILE + s),          Bh + g);
        cp16(sptr(sm + 2 * A_TILE + B_TILE + s), Bl + g);
    }
}

__global__ __launch_bounds__(256) void mma_gemm(
    const __nv_bfloat16* __restrict__ Ah, const __nv_bfloat16* __restrict__ Al,
    const __nv_bfloat16* __restrict__ Bh, const __nv_bfloat16* __restrict__ Bl,
    float* __restrict__ C, int M, int N, int K)
{
    extern __shared__ __nv_bfloat16 sm[];
    const int t = threadIdx.x, lane = t & 31, w = t >> 5;
    const int wm = w >> 2, wn = w & 3;
    const int m0 = blockIdx.y * BM, n0 = blockIdx.x * BN;

    float acc[4][4][4];
    #pragma unroll
    for (int i = 0; i < 4; i++)
        #pragma unroll
        for (int j = 0; j < 4; j++)
            #pragma unroll
            for (int r = 0; r < 4; r++) acc[i][j][r] = 0.f;

    const int g8 = lane >> 3;
    const int l8 = lane & 7;

    load_tile(sm, Ah, Al, Bh, Bl, K, N, m0, n0, 0, t);
    asm volatile("cp.async.commit_group;\n");

    const int nk = K / BK;
    for (int kt = 0; kt < nk; kt++) {
        __nv_bfloat16* buf = sm + (kt & 1) * BUF_ELEMS;
        if (kt + 1 < nk) {
            load_tile(sm + ((kt + 1) & 1) * BUF_ELEMS, Ah, Al, Bh, Bl,
                      K, N, m0, n0, (kt + 1) * BK, t);
            asm volatile("cp.async.commit_group;\n");
            asm volatile("cp.async.wait_group 1;\n");
        } else {
            asm volatile("cp.async.wait_group 0;\n");
        }
        __syncthreads();

        #pragma unroll
        for (int ks = 0; ks < 2; ks++) {
            uint32_t ah[4][4], al[4][4], bh[4][2], bl[4][2];
            #pragma unroll
            for (int i = 0; i < 4; i++) {
                int row = wm * 64 + i * 16 + (g8 & 1) * 8 + l8;
                int col = ks * 16 + (g8 >> 1) * 8;
                ldsm_x4(ah[i], sptr(buf + row * ASTRIDE + col));
                ldsm_x4(al[i], sptr(buf + A_TILE + row * ASTRIDE + col));
            }
            #pragma unroll
            for (int jj = 0; jj < 2; jj++) {
                int krow = ks * 16 + (g8 & 1) * 8 + l8;
                int ncol = wn * 32 + jj * 16 + (g8 >> 1) * 8;
                uint32_t r4[4];
                ldsm_x4_t(r4, sptr(buf + 2 * A_TILE + krow * BSTRIDE + ncol));
                bh[2 * jj][0] = r4[0]; bh[2 * jj][1] = r4[1];
                bh[2 * jj + 1][0] = r4[2]; bh[2 * jj + 1][1] = r4[3];
                ldsm_x4_t(r4, sptr(buf + 2 * A_TILE + B_TILE + krow * BSTRIDE + ncol));
                bl[2 * jj][0] = r4[0]; bl[2 * jj][1] = r4[1];
                bl[2 * jj + 1][0] = r4[2]; bl[2 * jj + 1][1] = r4[3];
            }
            #pragma unroll
            for (int i = 0; i < 4; i++)
                #pragma unroll
                for (int j = 0; j < 4; j++) {
                    mma16816(acc[i][j], ah[i], bh[j]);
                    mma16816(acc[i][j], ah[i], bl[j]);
                    mma16816(acc[i][j], al[i], bh[j]);
                }
        }
        __syncthreads();
    }

    #pragma unroll
    for (int i = 0; i < 4; i++)
        #pragma unroll
        for (int j = 0; j < 4; j++) {
            int row = m0 + wm * 64 + i * 16 + (lane >> 2);
            int col = n0 + wn * 32 + j * 8 + (lane & 3) * 2;
            *(float2*)&C[(size_t)row * N + col] =
                make_float2(acc[i][j][0], acc[i][j][1]);
            *(float2*)&C[(size_t)(row + 8) * N + col] =
                make_float2(acc[i][j][2], acc[i][j][3]);
        }
}

// ---------------- fused RoPE + bf16 hi/lo split ----------------
// heads 0..31: q (rope + 1/8 scale); 32..39: k (rope); 40..47: v (split only)
__global__ void rope_split_k(const float* __restrict__ q,
                             const float* __restrict__ kv,
                             const int* __restrict__ pos_ids,
                             __nv_bfloat16* __restrict__ qh, __nv_bfloat16* __restrict__ ql,
                             __nv_bfloat16* __restrict__ kh, __nv_bfloat16* __restrict__ kl,
                             __nv_bfloat16* __restrict__ vh, __nv_bfloat16* __restrict__ vl)
{
    int idx = blockIdx.x * blockDim.x + threadIdx.x;
    const int total = S_LEN * 48 * 32;
    if (idx >= total) return;

    int d    = idx & 31;
    int rest = idx >> 5;
    int hh   = rest % 48;
    int s    = rest / 48;

    if (hh < 40) {
        float pos = (float)pos_ids[s];
        float inv = __powf(10000.0f, -(float)d * (1.0f / 32.0f));
        float ang = pos * inv;
        float c, sn;
        __sincosf(ang, &sn, &c);
        float x1, x2, sc;
        size_t o1, o2;
        if (hh < 32) {
            const float* p = q + (size_t)s * HID + hh * HD;
            x1 = p[d]; x2 = p[d + 32]; sc = 0.125f;
            o1 = (size_t)s * HID + hh * HD + d; o2 = o1 + 32;
            float y1 = (x1 * c - x2 * sn) * sc;
            float y2 = (x2 * c + x1 * sn) * sc;
            __nv_bfloat16 h1 = __float2bfloat16(y1), h2 = __float2bfloat16(y2);
            qh[o1] = h1; ql[o1] = __float2bfloat16(y1 - __bfloat162float(h1));
            qh[o2] = h2; ql[o2] = __float2bfloat16(y2 - __bfloat162float(h2));
        } else {
            const float* p = kv + (size_t)s * KVW + (hh - 32) * HD;
            x1 = p[d]; x2 = p[d + 32];
            o1 = (size_t)s * 512 + (hh - 32) * HD + d; o2 = o1 + 32;
            float y1 = x1 * c - x2 * sn;
            float y2 = x2 * c + x1 * sn;
            __nv_bfloat16 h1 = __float2bfloat16(y1), h2 = __float2bfloat16(y2);
            kh[o1] = h1; kl[o1] = __float2bfloat16(y1 - __bfloat162float(h1));
            kh[o2] = h2; kl[o2] = __float2bfloat16(y2 - __bfloat162float(h2));
        }
    } else {
        const float* p = kv + (size_t)s * KVW + 512 + (hh - 40) * HD;
        float x1 = p[d], x2 = p[d + 32];
        size_t o1 = (size_t)s * 512 + (hh - 40) * HD + d, o2 = o1 + 32;
        __nv_bfloat16 h1 = __float2bfloat16(x1), h2 = __float2bfloat16(x2);
        vh[o1] = h1; vl[o1] = __float2bfloat16(x1 - __bfloat162float(h1));
        vh[o2] = h2; vl[o2] = __float2bfloat16(x2 - __bfloat162float(h2));
    }
}

// ---------------- tensor-core flash attention (causal) ----------------
// CTA: 128 q-rows x 1 head; 8 warps, 16 rows each. K-tiles of 64 keys.
// Smem: Qhi/Qlo [128][72], double-buffered K/V hi/lo [64][72] each.
#define AST 72                       // row stride (elems) -> 144B
#define QHI_OFF 0
#define QLO_OFF (128 * 144)          // 18432
#define BUF_OFF (2 * 128 * 144)      // 36864
#define KVBUF   (4 * 64 * 144)       // 36864 per buffer (khi,klo,vhi,vlo)
#define ATTN_SMEM (BUF_OFF + 2 * KVBUF)  // 110592

__device__ __forceinline__ void attn_load_kv(
    uint32_t bufb,
    const __nv_bfloat16* __restrict__ kh, const __nv_bfloat16* __restrict__ kl,
    const __nv_bfloat16* __restrict__ vh, const __nv_bfloat16* __restrict__ vl,
    int k0, int kvh, int t)
{
    #pragma unroll
    for (int i = 0; i < 2; i++) {
        int idx = i * 256 + t;
        int row = idx >> 3, cc = idx & 7;
        uint32_t off = (uint32_t)(row * 144 + cc * 16);
        size_t g = (size_t)(k0 + row) * 512 + kvh * HD + cc * 8;
        cp16(bufb + off,             kh + g);
        cp16(bufb + 9216 + off,      kl + g);
        cp16(bufb + 18432 + off,     vh + g);
        cp16(bufb + 27648 + off,     vl + g);
    }
}

__global__ __launch_bounds__(256) void attn_tc(
    const __nv_bfloat16* __restrict__ qh, const __nv_bfloat16* __restrict__ ql,
    const __nv_bfloat16* __restrict__ kh, const __nv_bfloat16* __restrict__ kl,
    const __nv_bfloat16* __restrict__ vh, const __nv_bfloat16* __restrict__ vl,
    __nv_bfloat16* __restrict__ Oh, __nv_bfloat16* __restrict__ Ol)
{
    extern __shared__ __align__(1024) char asmem[];
    const uint32_t sb = sptr(asmem);
    const int qt  = 15 - blockIdx.x;        // big tiles first
    const int h   = blockIdx.y;
    const int kvh = h >> 2;
    const int t = threadIdx.x, w = t >> 5, lane = t & 31;
    const int g8 = lane >> 3, l8 = lane & 7, tig = lane & 3, g = lane >> 2;
    const int q0 = qt * 128;

    // load Q tile (hi/lo) + K/V tile 0
    #pragma unroll
    for (int i = 0; i < 4; i++) {
        int idx = i * 256 + t;
        int row = idx >> 3, cc = idx & 7;
        uint32_t off = (uint32_t)(row * 144 + cc * 16);
        size_t gg = (size_t)(q0 + row) * HID + h * HD + cc * 8;
        cp16(sb + QHI_OFF + off, qh + gg);
        cp16(sb + QLO_OFF + off, ql + gg);
    }
    attn_load_kv(sb + BUF_OFF, kh, kl, vh, vl, 0, kvh, t);
    asm volatile("cp.async.commit_group;\n");
    asm volatile("cp.async.wait_group 0;\n");
    __syncthreads();

    // Q frags to registers (A-operand, rows w*16..+15)
    uint32_t qah[4][4], qal[4][4];
    #pragma unroll
    for (int kc = 0; kc < 4; kc++) {
        uint32_t off = (uint32_t)((w * 16 + (g8 & 1) * 8 + l8) * 144 +
                                  (kc * 16 + (g8 >> 1) * 8) * 2);
        ldsm_x4(qah[kc], sb + QHI_OFF + off);
        ldsm_x4(qal[kc], sb + QLO_OFF + off);
    }

    float oacc[8][4];
    #pragma unroll
    for (int j = 0; j < 8; j++)
        #pragma unroll
        for (int r = 0; r < 4; r++) oacc[j][r] = 0.f;
    float m0 = -1e30f, m1 = -1e30f, l0 = 0.f, l1 = 0.f;

    const int row0 = q0 + w * 16 + g;
    const int row1 = row0 + 8;
    const int nkt = 2 * qt + 2;

    for (int kt = 0; kt < nkt; kt++) {
        const uint32_t buf = sb + BUF_OFF + (uint32_t)(kt & 1) * KVBUF;
        if (kt + 1 < nkt) {
            attn_load_kv(sb + BUF_OFF + (uint32_t)((kt + 1) & 1) * KVBUF,
                         kh, kl, vh, vl, (kt + 1) * 64, kvh, t);
            asm volatile("cp.async.commit_group;\n");
            asm volatile("cp.async.wait_group 1;\n");
        } else {
            asm volatile("cp.async.wait_group 0;\n");
        }
        __syncthreads();

        // ---- S = Q K^T (3-pass) ----
        float sacc[8][4];
        #pragma unroll
        for (int j = 0; j < 8; j++)
            #pragma unroll
            for (int r = 0; r < 4; r++) sacc[j][r] = 0.f;

        #pragma unroll
        for (int kg = 0; kg < 4; kg++) {        // 16-key groups
            #pragma unroll
            for (int kc = 0; kc < 4; kc++) {    // hd chunks of 16
                uint32_t off = (uint32_t)((kg * 16 + (g8 & 1) * 8 + l8) * 144 +
                                          (kc * 16 + (g8 >> 1) * 8) * 2);
                uint32_t kbh[4], kbl[4];
                ldsm_x4(kbh, buf + off);
                ldsm_x4(kbl, buf + 9216 + off);
                uint32_t b0h[2] = {kbh[0], kbh[2]}, b1h[2] = {kbh[1], kbh[3]};
                uint32_t b0l[2] = {kbl[0], kbl[2]}, b1l[2] = {kbl[1], kbl[3]};
                mma16816(sacc[2 * kg],     qah[kc], b0h);
                mma16816(sacc[2 * kg],     qah[kc], b0l);
                mma16816(sacc[2 * kg],     qal[kc], b0h);
                mma16816(sacc[2 * kg + 1], qah[kc], b1h);
                mma16816(sacc[2 * kg + 1], qah[kc], b1l);
                mma16816(sacc[2 * kg + 1], qal[kc], b1h);
            }
        }

        // ---- causal mask (diagonal tiles only) ----
        if (kt >= 2 * qt) {
            #pragma unroll
            for (int j = 0; j < 8; j++) {
                int col = kt * 64 + j * 8 + tig * 2;
                if (col > row0)     sacc[j][0] = -1e30f;
                if (col + 1 > row0) sacc[j][1] = -1e30f;
                if (col > row1)     sacc[j][2] = -1e30f;
                if (col + 1 > row1) sacc[j][3] = -1e30f;
            }
        }

        // ---- online softmax ----
        float mx0 = -1e30f, mx1 = -1e30f;
        #pragma unroll
        for (int j = 0; j < 8; j++) {
            mx0 = fmaxf(mx0, fmaxf(sacc[j][0], sacc[j][1]));
            mx1 = fmaxf(mx1, fmaxf(sacc[j][2], sacc[j][3]));
        }
        mx0 = fmaxf(mx0, __shfl_xor_sync(0xffffffffu, mx0, 1));
        mx0 = fmaxf(mx0, __shfl_xor_sync(0xffffffffu, mx0, 2));
        mx1 = fmaxf(mx1, __shfl_xor_sync(0xffffffffu, mx1, 1));
        mx1 = fmaxf(mx1, __shfl_xor_sync(0xffffffffu, mx1, 2));

        float nm0 = fmaxf(m0, mx0), nm1 = fmaxf(m1, mx1);
        float al0 = __expf(m0 - nm0), al1 = __expf(m1 - nm1);
        m0 = nm0; m1 = nm1;

        float rs0 = 0.f, rs1 = 0.f;
        #pragma unroll
        for (int j = 0; j < 8; j++) {
            sacc[j][0] = __expf(sacc[j][0] - nm0);
            sacc[j][1] = __expf(sacc[j][1] - nm0);
            sacc[j][2] = __expf(sacc[j][2] - nm1);
            sacc[j][3] = __expf(sacc[j][3] - nm1);
            rs0 += sacc[j][0] + sacc[j][1];
            rs1 += sacc[j][2] + sacc[j][3];
        }
        rs0 += __shfl_xor_sync(0xffffffffu, rs0, 1);
        rs0 += __shfl_xor_sync(0xffffffffu, rs0, 2);
        rs1 += __shfl_xor_sync(0xffffffffu, rs1, 1);
        rs1 += __shfl_xor_sync(0xffffffffu, rs1, 2);
        l0 = l0 * al0 + rs0;
        l1 = l1 * al1 + rs1;
        #pragma unroll
        for (int j = 0; j < 8; j++) {
            oacc[j][0] *= al0; oacc[j][1] *= al0;
            oacc[j][2] *= al1; oacc[j][3] *= al1;
        }

        // ---- pack P to bf16 hi/lo A-frags (register reuse of C layout) ----
        uint32_t pah[4][4], pal[4][4];
        #pragma unroll
        for (int kc = 0; kc < 4; kc++) {
            int j0 = 2 * kc, j1 = 2 * kc + 1;
            float p00 = sacc[j0][0], p01 = sacc[j0][1];
            float p02 = sacc[j0][2], p03 = sacc[j0][3];
            float p10 = sacc[j1][0], p11 = sacc[j1][1];
            float p12 = sacc[j1][2], p13 = sacc[j1][3];
            float h00 = __bfloat162float(__float2bfloat16(p00));
            float h01 = __bfloat162float(__float2bfloat16(p01));
            float h02 = __bfloat162float(__float2bfloat16(p02));
            float h03 = __bfloat162float(__float2bfloat16(p03));
            float h10 = __bfloat162float(__float2bfloat16(p10));
            float h11 = __bfloat162float(__float2bfloat16(p11));
            float h12 = __bfloat162float(__float2bfloat16(p12));
            float h13 = __bfloat162float(__float2bfloat16(p13));
            pah[kc][0] = packbf2(h00, h01);
            pah[kc][1] = packbf2(h02, h03);
            pah[kc][2] = packbf2(h10, h11);
            pah[kc][3] = packbf2(h12, h13);
            pal[kc][0] = packbf2(p00 - h00, p01 - h01);
            pal[kc][1] = packbf2(p02 - h02, p03 - h03);
            pal[kc][2] = packbf2(p10 - h10, p11 - h11);
            pal[kc][3] = packbf2(p12 - h12, p13 - h13);
        }

        // ---- O += P V (3-pass) ----
        #pragma unroll
        for (int kc = 0; kc < 4; kc++) {        // 16-key chunks
            #pragma unroll
            for (int jj = 0; jj < 4; jj++) {    // hd col pairs of 16
                uint32_t off = (uint32_t)((kc * 16 + (g8 & 1) * 8 + l8) * 144 +
                                          (jj * 16 + (g8 >> 1) * 8) * 2);
                uint32_t vbh[4], vbl[4];
                ldsm_x4_t(vbh, buf + 18432 + off);
                ldsm_x4_t(vbl, buf + 27648 + off);
                uint32_t b0h[2] = {vbh[0], vbh[1]}, b1h[2] = {vbh[2], vbh[3]};
                uint32_t b0l[2] = {vbl[0], vbl[1]}, b1l[2] = {vbl[2], vbl[3]};
                mma16816(oacc[2 * jj],     pah[kc], b0h);
                mma16816(oacc[2 * jj],     pah[kc], b0l);
                mma16816(oacc[2 * jj],     pal[kc], b0h);
                mma16816(oacc[2 * jj + 1], pah[kc], b1h);
                mma16816(oacc[2 * jj + 1], pah[kc], b1l);
                mma16816(oacc[2 * jj + 1], pal[kc], b1h);
            }
        }
        __syncthreads();
    }

    // ---- epilogue: O/l -> bf16 hi/lo ----
    float i0 = 1.0f / l0, i1 = 1.0f / l1;
    #pragma unroll
    for (int j = 0; j < 8; j++) {
        int col = h * HD + j * 8 + tig * 2;
        float o0 = oacc[j][0] * i0, o1 = oacc[j][1] * i0;
        float o2 = oacc[j][2] * i1, o3 = oacc[j][3] * i1;
        float h0 = __bfloat162float(__float2bfloat16(o0));
        float h1 = __bfloat162float(__float2bfloat16(o1));
        float h2 = __bfloat162float(__float2bfloat16(o2));
        float h3 = __bfloat162float(__float2bfloat16(o3));
        *(uint32_t*)&Oh[(size_t)row0 * HID + col] = packbf2(h0, h1);
        *(uint32_t*)&Oh[(size_t)row1 * HID + col] = packbf2(h2, h3);
        *(uint32_t*)&Ol[(size_t)row0 * HID + col] = packbf2(o0 - h0, o1 - h1);
        *(uint32_t*)&Ol[(size_t)row1 * HID + col] = packbf2(o2 - h2, o3 - h3);
    }
}

// ---------------- launch ----------------
extern "C" void kernel_launch(void* const* d_in, const int* in_sizes, int n_in,
                              void* d_out, int out_size)
{
    const float* X   = (const float*)d_in[0];
    const int*   pid = (const int*)d_in[2];
    const float* Wq  = (const float*)d_in[3];
    const float* Wk  = (const float*)d_in[4];
    const float* Wv  = (const float*)d_in[5];
    const float* Wo  = (const float*)d_in[6];
    float* out = (float*)d_out;

    float *q, *kv;
    cudaGetSymbolAddress((void**)&q,  g_q);
    cudaGetSymbolAddress((void**)&kv, g_kv);
    __nv_bfloat16 *Xh, *Xl, *Wqh, *Wql, *Wkvh, *Wkvl, *Woh, *Wol, *Ah, *Al;
    __nv_bfloat16 *qh, *ql, *kh, *kl, *vh, *vl;
    cudaGetSymbolAddress((void**)&Xh,  g_Xhi);   cudaGetSymbolAddress((void**)&Xl,  g_Xlo);
    cudaGetSymbolAddress((void**)&Wqh, g_Wqhi);  cudaGetSymbolAddress((void**)&Wql, g_Wqlo);
    cudaGetSymbolAddress((void**)&Wkvh,g_Wkvhi); cudaGetSymbolAddress((void**)&Wkvl,g_Wkvlo);
    cudaGetSymbolAddress((void**)&Woh, g_Wohi);  cudaGetSymbolAddress((void**)&Wol, g_Wolo);
    cudaGetSymbolAddress((void**)&Ah,  g_Ahi);   cudaGetSymbolAddress((void**)&Al,  g_Alo);
    cudaGetSymbolAddress((void**)&qh,  g_qh);    cudaGetSymbolAddress((void**)&ql,  g_ql);
    cudaGetSymbolAddress((void**)&kh,  g_kh);    cudaGetSymbolAddress((void**)&kl,  g_kl);
    cudaGetSymbolAddress((void**)&vh,  g_vh);    cudaGetSymbolAddress((void**)&vl,  g_vl);

    cudaFuncSetAttribute(mma_gemm, cudaFuncAttributeMaxDynamicSharedMemorySize,
                         GEMM_SMEM_BYTES);
    cudaFuncSetAttribute(attn_tc, cudaFuncAttributeMaxDynamicSharedMemorySize,
                         ATTN_SMEM);

    // splits
    split_k<<<(S_LEN * HID) / 256, 256>>>(X,  Xh,  Xl,  S_LEN * HID);
    split_k<<<(HID * HID) / 256, 256>>>(Wq, Wqh, Wql, HID * HID);
    split_pack_k<<<(HID * 512) / 256, 256>>>(Wk, Wkvh, Wkvl, HID, 512, KVW, 0);
    split_pack_k<<<(HID * 512) / 256, 256>>>(Wv, Wkvh, Wkvl, HID, 512, KVW, 512);
    split_k<<<(HID * HID) / 256, 256>>>(Wo, Woh, Wol, HID * HID);

    // projections
    mma_gemm<<<dim3(HID / BN, S_LEN / BM), 256, GEMM_SMEM_BYTES>>>(
        Xh, Xl, Wqh, Wql, q, S_LEN, HID, HID);
    mma_gemm<<<dim3(KVW / BN, S_LEN / BM), 256, GEMM_SMEM_BYTES>>>(
        Xh, Xl, Wkvh, Wkvl, kv, S_LEN, KVW, HID);

    // RoPE + split to bf16 hi/lo
    {
        int total = S_LEN * 48 * 32;
        rope_split_k<<<(total + 255) / 256, 256>>>(q, kv, pid, qh, ql, kh, kl, vh, vl);
    }

    // tensor-core causal flash attention -> Ahi/Alo
    attn_tc<<<dim3(16, NH), 256, ATTN_SMEM>>>(qh, ql, kh, kl, vh, vl, Ah, Al);

    // output projection
    mma_gemm<<<dim3(HID / BN, S_LEN / BM), 256, GEMM_SMEM_BYTES>>>(
        Ah, Al, Woh, Wol, out, S_LEN, HID, HID);
}